// round 7
// baseline (speedup 1.0000x reference)
#include <cuda_runtime.h>

// B=256 batches, N=128 neurons, E=4N=512 state dims.
// Output layout: [ydot (B*512 floats)] [J (B*512*512 floats)]
#define NN 128
#define BB 256
#define EE 512
#define NB 8            // batches per point-block (2 halves x 4 iterations)

// -------- scratch (__device__ globals; no allocations allowed) --------
__device__ float  g_negGCC[NN * NN];     // -g_C[i][j] / C[j], row-major (i major)
__device__ float  g_sumGC;               // sum over all i,j of g_C[i][j]/C[j]
__device__ float4 g_state [BB * NN];     // {dvv, jm, jh, jn} per (b,i)

// ---------------------------------------------------------------------
// Kernel 1: fused prep + HH dynamics + coupling matvec, multi-batch.
// Grid: BB/NB = 32 blocks x 256 threads. Block stages the whole
// w[i][j] = gC[i][j]*invC[j] tile into shared memory ONCE (coalesced,
// high-MLP), then each half-block (sub = tid>>7) processes 4 batches.
// Side duties (deterministic):
//   every block bx : spill its 512-element slice of -w into g_negGCC
//   block 0        : fixed-order tree reduce of staged sums -> g_sumGC
// ---------------------------------------------------------------------
extern __shared__ float sm[];   // w[NN*NN] | invCs[NN] | Vs[2*NN] | red[256]

__global__ void __launch_bounds__(256)
point_multi_kernel(const float* __restrict__ y,     const float* __restrict__ Ic,
                   const float* __restrict__ C,
                   const float* __restrict__ g_Na,  const float* __restrict__ E_Na,
                   const float* __restrict__ g_K,   const float* __restrict__ E_K,
                   const float* __restrict__ g_L,   const float* __restrict__ E_L,
                   const float* __restrict__ m_inf, const float* __restrict__ tau_m,
                   const float* __restrict__ h_inf, const float* __restrict__ tau_h,
                   const float* __restrict__ n_inf, const float* __restrict__ tau_n,
                   const float* __restrict__ gC,
                   float* __restrict__ ydot) {
    float* w     = sm;                    // [NN*NN]
    float* invCs = sm + NN * NN;          // [NN]
    float* Vs    = invCs + NN;            // [2][NN]
    float* red   = Vs + 2 * NN;           // [256]

    const int tid = threadIdx.x;
    const int i   = tid & 127;            // neuron
    const int sub = tid >> 7;             // half-block 0/1

    if (tid < NN) invCs[tid] = 1.f / C[tid];
    __syncthreads();

    // ---- stage w (coalesced, 64 elements/thread, fixed order) ----
    float colacc = 0.f;
    #pragma unroll 8
    for (int e = tid; e < NN * NN; e += 256) {
        float v = gC[e] * invCs[e & 127];
        w[e] = v;
        colacc += v;
    }
    __syncthreads();

    // ---- spill this block's slice of -w to global (for fill) ----
    {
        int e0 = blockIdx.x * 512 + tid;
        g_negGCC[e0]       = -w[e0];
        g_negGCC[e0 + 256] = -w[e0 + 256];
    }

    // ---- sumGC: block 0, deterministic tree over 256 fixed partials ----
    if (blockIdx.x == 0) {
        red[tid] = colacc;
        __syncthreads();
        #pragma unroll
        for (int s = 128; s > 0; s >>= 1) {
            if (tid < s) red[tid] += red[tid + s];
            __syncthreads();
        }
        if (tid == 0) g_sumGC = red[0];
    }

    // ---- per-neuron constants (loaded once, reused for 4 batches) ----
    const float invC = invCs[i];
    const float gna = g_Na[i], gk = g_K[i], gl = g_L[i];
    const float ena = E_Na[i], ek = E_K[i], el = E_L[i];
    const float mi = m_inf[i], hi = h_inf[i], ni = n_inf[i];
    const float tm = tau_m[i], th = tau_h[i], tn = tau_n[i];
    const float* wrow = w + i * NN;

    // ---- batch loop: half-block sub handles batches bx*8 + q*2 + sub ----
    for (int q = 0; q < 4; q++) {
        const int b = blockIdx.x * NB + q * 2 + sub;

        float4 yv = reinterpret_cast<const float4*>(y)[b * NN + i];
        float V = yv.x, m = yv.y, h = yv.z, n = yv.w;

        __syncthreads();                  // Vs free to overwrite
        Vs[sub * NN + i] = V;
        __syncthreads();

        const float* vsub = Vs + sub * NN;
        float a0 = 0.f, a1 = 0.f, a2 = 0.f, a3 = 0.f;
        #pragma unroll 8
        for (int k = 0; k < NN; k += 4) {
            int j0 = (k + 0 + i) & 127;   // staggered: conflict-free banks
            int j1 = (k + 1 + i) & 127;
            int j2 = (k + 2 + i) & 127;
            int j3 = (k + 3 + i) & 127;
            a0 = fmaf(wrow[j0], V - vsub[j0], a0);
            a1 = fmaf(wrow[j1], V - vsub[j1], a1);
            a2 = fmaf(wrow[j2], V - vsub[j2], a2);
            a3 = fmaf(wrow[j3], V - vsub[j3], a3);
        }
        float acc = (a0 + a1) + (a2 + a3);

        float m2 = m * m, m3 = m2 * m;
        float n2 = n * n, n3 = n2 * n, n4 = n3 * n;
        float dVNa = V - ena;
        float dVK  = V - ek;

        float Vdot = invC * (-gna * m3 * h * dVNa - gk * n4 * dVK - gl * (V - el) + Ic[b]) + acc;
        float mdot = (mi - m) / tm;
        float hdot = (hi - h) / th;
        float ndot = (ni - n) / tn;

        reinterpret_cast<float4*>(ydot)[b * NN + i] = make_float4(Vdot, mdot, hdot, ndot);

        float dvv = invC * (-gl - gna * h * m3 - gk * n4);
        float jm  = -invC * 3.f * gna * h * m2 * dVNa;
        float jh  = -invC * gna * m3 * dVNa;
        float jn  = -invC * 4.f * gk * n3 * dVK;
        g_state[b * NN + i] = make_float4(dvv, jm, jh, jn);
    }
}

// ---------------------------------------------------------------------
// Kernel 2: stream-fill the full Jacobian (268 MB of STG.128).
// Store structure identical to the 37.5us/70% DRAM kernel; the comp>0
// diagonal now computes -1/tau inline (g_diag4 removed).
// Grid: x = 256 row-pairs, y = 128 batch-pairs. Block = 256 threads.
// ---------------------------------------------------------------------
__global__ void __launch_bounds__(256)
fill_kernel(float* __restrict__ J,
            const float* __restrict__ tau_m,
            const float* __restrict__ tau_h,
            const float* __restrict__ tau_n) {
    const int j    = threadIdx.x & 127;
    const int half = threadIdx.x >> 7;            // 0 or 1
    const int r    = blockIdx.x * 2 + half;       // 0..511  (warp-uniform)
    const int b    = blockIdx.y;                  // batches b and b+128
    const int comp = r & 3;
    const int i    = r >> 2;

    float4 o0 = make_float4(0.f, 0.f, 0.f, 0.f);
    if (comp == 0) o0.x = g_negGCC[i * NN + j];   // coalesced across warp
    float4 o1 = o0;

    if (j == i) {
        if (comp == 0) {
            float s = g_sumGC;
            float4 s0 = g_state[b * NN + i];
            float4 s1 = g_state[(b + 128) * NN + i];
            o0.x += s + s0.x; o0.y = s0.y; o0.z = s0.z; o0.w = s0.w;
            o1.x += s + s1.x; o1.y = s1.y; o1.z = s1.z; o1.w = s1.w;
        } else {
            const float* tau = (comp == 1) ? tau_m : (comp == 2) ? tau_h : tau_n;
            float val = -1.f / tau[i];
            reinterpret_cast<float*>(&o0)[comp] = val;
            reinterpret_cast<float*>(&o1)[comp] = val;
        }
    }

    unsigned idx0 = (unsigned)b * (EE * NN) + (unsigned)r * NN + j;
    unsigned idx1 = idx0 + 128u * (EE * NN);
    __stcs(reinterpret_cast<float4*>(J) + idx0, o0);
    __stcs(reinterpret_cast<float4*>(J) + idx1, o1);
}

// ---------------------------------------------------------------------
extern "C" void kernel_launch(void* const* d_in, const int* in_sizes, int n_in,
                              void* d_out, int out_size) {
    const float* y     = (const float*)d_in[0];
    const float* Ic    = (const float*)d_in[1];
    const float* C     = (const float*)d_in[2];
    const float* g_Na  = (const float*)d_in[3];
    const float* E_Na  = (const float*)d_in[4];
    const float* g_K   = (const float*)d_in[5];
    const float* E_K   = (const float*)d_in[6];
    const float* g_L   = (const float*)d_in[7];
    const float* E_L   = (const float*)d_in[8];
    const float* m_inf = (const float*)d_in[9];
    const float* tau_m = (const float*)d_in[10];
    const float* h_inf = (const float*)d_in[11];
    const float* tau_h = (const float*)d_in[12];
    const float* n_inf = (const float*)d_in[13];
    const float* tau_n = (const float*)d_in[14];
    const float* g_C   = (const float*)d_in[15];

    float* out  = (float*)d_out;
    float* ydot = out;                       // B*512 floats
    float* J    = out + (size_t)BB * EE;     // B*512*512 floats

    // w + invCs + Vs(2x128) + red(256) floats
    const int smemBytes = (NN * NN + NN + 2 * NN + 256) * sizeof(float);
    cudaFuncSetAttribute(point_multi_kernel,
                         cudaFuncAttributeMaxDynamicSharedMemorySize, smemBytes);

    point_multi_kernel<<<BB / NB, 256, smemBytes>>>(
        y, Ic, C, g_Na, E_Na, g_K, E_K, g_L, E_L,
        m_inf, tau_m, h_inf, tau_h, n_inf, tau_n, g_C, ydot);

    fill_kernel<<<dim3(EE / 2, BB / 2), 256>>>(J, tau_m, tau_h, tau_n);
}

// round 8
// speedup vs baseline: 1.1219x; 1.1219x over previous
#include <cuda_runtime.h>

// B=256 batches, N=128 neurons, E=4N=512 state dims.
// Output layout: [ydot (B*512 floats)] [J (B*512*512 floats)]
#define NN 128
#define BB 256
#define EE 512

// -------- scratch (__device__ globals; no allocations allowed) --------
__device__ float  g_negGCC[NN * NN];     // -g_C[i][j] / C[j], row-major (i major)
__device__ float  g_sumGC;               // sum over all i,j of g_C[i][j]/C[j]
__device__ float4 g_diag4 [NN];          // {0, -1/tau_m, -1/tau_h, -1/tau_n}
__device__ float4 g_state [BB * NN];     // {dvv, jm, jh, jn} per (b,i)

// ---------------------------------------------------------------------
// Kernel 1: fused prep + HH dynamics + coupling matvec.
// Grid: BB/2 = 128 blocks x 256 threads. Each block stages the whole
// w[i][j] = gC[i][j]*invC[j] tile (64 strided elements/thread, 8 warps
// of MLP) then each HALF-BLOCK (sub = tid>>7) handles one batch:
// b = bx*2 + sub. No batch loop, minimal syncs, ~86% of SMs busy.
// Side duties (deterministic):
//   block bx : spill row bx of -w into g_negGCC   (bx = 0..127)
//   block 0  : fixed-order tree reduce -> g_sumGC
//   block 1  : build g_diag4 from tau arrays
// ---------------------------------------------------------------------
extern __shared__ float sm[];   // w[NN*NN] | invCs[NN] | Vs[2*NN] | red[256]

__global__ void __launch_bounds__(256)
point_kernel(const float* __restrict__ y,     const float* __restrict__ Ic,
             const float* __restrict__ C,
             const float* __restrict__ g_Na,  const float* __restrict__ E_Na,
             const float* __restrict__ g_K,   const float* __restrict__ E_K,
             const float* __restrict__ g_L,   const float* __restrict__ E_L,
             const float* __restrict__ m_inf, const float* __restrict__ tau_m,
             const float* __restrict__ h_inf, const float* __restrict__ tau_h,
             const float* __restrict__ n_inf, const float* __restrict__ tau_n,
             const float* __restrict__ gC,
             float* __restrict__ ydot) {
    float* w     = sm;                    // [NN*NN]
    float* invCs = sm + NN * NN;          // [NN]
    float* Vs    = invCs + NN;            // [2][NN]
    float* red   = Vs + 2 * NN;           // [256]

    const int tid = threadIdx.x;
    const int i   = tid & 127;            // neuron
    const int sub = tid >> 7;             // half-block 0/1
    const int b   = blockIdx.x * 2 + sub; // this thread's batch

    if (tid < NN) invCs[tid] = 1.f / C[tid];

    // Load own state early (independent of staging).
    float4 yv = reinterpret_cast<const float4*>(y)[b * NN + i];
    float V = yv.x, m = yv.y, h = yv.z, n = yv.w;
    Vs[sub * NN + i] = V;
    __syncthreads();                      // invCs + Vs ready

    // ---- stage w: 64 strided elements/thread, fixed order ----
    float colacc = 0.f;
    #pragma unroll 8
    for (int e = tid; e < NN * NN; e += 256) {
        float v = gC[e] * invCs[e & 127];
        w[e] = v;
        colacc += v;
    }
    __syncthreads();                      // w ready

    // ---- side duties ----
    if (tid < NN)                         // spill row bx of -w (coalesced)
        g_negGCC[blockIdx.x * NN + tid] = -w[blockIdx.x * NN + tid];

    if (blockIdx.x == 0) {                // deterministic sumGC tree
        red[tid] = colacc;
        __syncthreads();
        #pragma unroll
        for (int s = 128; s > 0; s >>= 1) {
            if (tid < s) red[tid] += red[tid + s];
            __syncthreads();
        }
        if (tid == 0) g_sumGC = red[0];
    }
    if (blockIdx.x == 1 && tid < NN)
        g_diag4[tid] = make_float4(0.f, -1.f / tau_m[tid], -1.f / tau_h[tid], -1.f / tau_n[tid]);

    // ---- coupling matvec: staggered conflict-free shared reads ----
    const float* wrow = w + i * NN;
    const float* vsub = Vs + sub * NN;
    float a0 = 0.f, a1 = 0.f, a2 = 0.f, a3 = 0.f;
    #pragma unroll 8
    for (int k = 0; k < NN; k += 4) {
        int j0 = (k + 0 + i) & 127;
        int j1 = (k + 1 + i) & 127;
        int j2 = (k + 2 + i) & 127;
        int j3 = (k + 3 + i) & 127;
        a0 = fmaf(wrow[j0], V - vsub[j0], a0);
        a1 = fmaf(wrow[j1], V - vsub[j1], a1);
        a2 = fmaf(wrow[j2], V - vsub[j2], a2);
        a3 = fmaf(wrow[j3], V - vsub[j3], a3);
    }
    float acc = (a0 + a1) + (a2 + a3);

    const float invC = invCs[i];
    float gna = g_Na[i], gk = g_K[i], gl = g_L[i];
    float m2 = m * m, m3 = m2 * m;
    float n2 = n * n, n3 = n2 * n, n4 = n3 * n;
    float dVNa = V - E_Na[i];
    float dVK  = V - E_K[i];

    float Vdot = invC * (-gna * m3 * h * dVNa - gk * n4 * dVK - gl * (V - E_L[i]) + Ic[b]) + acc;
    float mdot = (m_inf[i] - m) / tau_m[i];
    float hdot = (h_inf[i] - h) / tau_h[i];
    float ndot = (n_inf[i] - n) / tau_n[i];

    reinterpret_cast<float4*>(ydot)[b * NN + i] = make_float4(Vdot, mdot, hdot, ndot);

    float dvv = invC * (-gl - gna * h * m3 - gk * n4);
    float jm  = -invC * 3.f * gna * h * m2 * dVNa;
    float jh  = -invC * gna * m3 * dVNa;
    float jn  = -invC * 4.f * gk * n3 * dVK;
    g_state[b * NN + i] = make_float4(dvv, jm, jh, jn);
}

// ---------------------------------------------------------------------
// Kernel 2: stream-fill the full Jacobian (268 MB of STG.128).
// EXACT R6 form (measured 37.47us @ 70.6% DRAM). Grid: x = 256
// row-pairs, y = 128 batch-pairs; 2 float4 stores per thread (b, b+128).
// ---------------------------------------------------------------------
__global__ void __launch_bounds__(256)
fill_kernel(float* __restrict__ J) {
    const int j    = threadIdx.x & 127;
    const int half = threadIdx.x >> 7;            // 0 or 1
    const int r    = blockIdx.x * 2 + half;       // 0..511  (warp-uniform)
    const int b    = blockIdx.y;                  // batches b and b+128
    const int comp = r & 3;
    const int i    = r >> 2;

    float4 o0 = make_float4(0.f, 0.f, 0.f, 0.f);
    if (comp == 0) o0.x = g_negGCC[i * NN + j];   // coalesced across warp
    float4 o1 = o0;

    if (j == i) {
        if (comp == 0) {
            float s = g_sumGC;
            float4 s0 = g_state[b * NN + i];
            float4 s1 = g_state[(b + 128) * NN + i];
            o0.x += s + s0.x; o0.y = s0.y; o0.z = s0.z; o0.w = s0.w;
            o1.x += s + s1.x; o1.y = s1.y; o1.z = s1.z; o1.w = s1.w;
        } else {
            float4 d = g_diag4[i];
            float val = (comp == 1) ? d.y : (comp == 2) ? d.z : d.w;
            reinterpret_cast<float*>(&o0)[comp] = val;
            reinterpret_cast<float*>(&o1)[comp] = val;
        }
    }

    unsigned idx0 = (unsigned)b * (EE * NN) + (unsigned)r * NN + j;
    unsigned idx1 = idx0 + 128u * (EE * NN);
    __stcs(reinterpret_cast<float4*>(J) + idx0, o0);
    __stcs(reinterpret_cast<float4*>(J) + idx1, o1);
}

// ---------------------------------------------------------------------
extern "C" void kernel_launch(void* const* d_in, const int* in_sizes, int n_in,
                              void* d_out, int out_size) {
    const float* y     = (const float*)d_in[0];
    const float* Ic    = (const float*)d_in[1];
    const float* C     = (const float*)d_in[2];
    const float* g_Na  = (const float*)d_in[3];
    const float* E_Na  = (const float*)d_in[4];
    const float* g_K   = (const float*)d_in[5];
    const float* E_K   = (const float*)d_in[6];
    const float* g_L   = (const float*)d_in[7];
    const float* E_L   = (const float*)d_in[8];
    const float* m_inf = (const float*)d_in[9];
    const float* tau_m = (const float*)d_in[10];
    const float* h_inf = (const float*)d_in[11];
    const float* tau_h = (const float*)d_in[12];
    const float* n_inf = (const float*)d_in[13];
    const float* tau_n = (const float*)d_in[14];
    const float* g_C   = (const float*)d_in[15];

    float* out  = (float*)d_out;
    float* ydot = out;                       // B*512 floats
    float* J    = out + (size_t)BB * EE;     // B*512*512 floats

    // w + invCs + Vs(2x128) + red(256) floats  (~66.5 KB)
    const int smemBytes = (NN * NN + NN + 2 * NN + 256) * sizeof(float);
    cudaFuncSetAttribute(point_kernel,
                         cudaFuncAttributeMaxDynamicSharedMemorySize, smemBytes);

    point_kernel<<<BB / 2, 256, smemBytes>>>(
        y, Ic, C, g_Na, E_Na, g_K, E_K, g_L, E_L,
        m_inf, tau_m, h_inf, tau_h, n_inf, tau_n, g_C, ydot);

    fill_kernel<<<dim3(EE / 2, BB / 2), 256>>>(J);
}

// round 9
// speedup vs baseline: 1.1816x; 1.0532x over previous
#include <cuda_runtime.h>

// B=256 batches, N=128 neurons, E=4N=512 state dims.
// Output layout: [ydot (B*512 floats)] [J (B*512*512 floats)]
#define NN 128
#define BB 256
#define EE 512

// -------- scratch (__device__ globals; no allocations allowed) --------
__device__ float  g_negGCC[NN * NN];     // -g_C[i][j] / C[j], row-major
__device__ float  g_sumGC;               // sum over all i,j of g_C[i][j]/C[j]
__device__ float4 g_state [BB * NN];     // {dvv, jm, jh, jn} per (b,i)

// -------- streams/events (static init; no device-memory allocation) ----
static cudaStream_t g_sA, g_sB;
static cudaEvent_t  g_eFork, g_eJoinB, g_eDone;
static struct _StreamInit {
    _StreamInit() {
        cudaFree(0);
        cudaStreamCreateWithFlags(&g_sA, cudaStreamNonBlocking);
        cudaStreamCreateWithFlags(&g_sB, cudaStreamNonBlocking);
        cudaEventCreateWithFlags(&g_eFork,  cudaEventDisableTiming);
        cudaEventCreateWithFlags(&g_eJoinB, cudaEventDisableTiming);
        cudaEventCreateWithFlags(&g_eDone,  cudaEventDisableTiming);
    }
} g_streamInit;

// ---------------------------------------------------------------------
// Kernel P: fused prep + HH dynamics + coupling matvec (R8 form).
// Grid: BB/2 = 128 blocks x 256 threads; half-block sub handles batch
// b = bx*2 + sub. Stages w = gC*invC once per block; deterministic.
// Side duties: block bx spills row bx of -w; block 0 reduces sumGC.
// ---------------------------------------------------------------------
extern __shared__ float sm[];   // w[NN*NN] | invCs[NN] | Vs[2*NN] | red[256]

__global__ void __launch_bounds__(256)
point_kernel(const float* __restrict__ y,     const float* __restrict__ Ic,
             const float* __restrict__ C,
             const float* __restrict__ g_Na,  const float* __restrict__ E_Na,
             const float* __restrict__ g_K,   const float* __restrict__ E_K,
             const float* __restrict__ g_L,   const float* __restrict__ E_L,
             const float* __restrict__ m_inf, const float* __restrict__ tau_m,
             const float* __restrict__ h_inf, const float* __restrict__ tau_h,
             const float* __restrict__ n_inf, const float* __restrict__ tau_n,
             const float* __restrict__ gC,
             float* __restrict__ ydot) {
    float* w     = sm;                    // [NN*NN]
    float* invCs = sm + NN * NN;          // [NN]
    float* Vs    = invCs + NN;            // [2][NN]
    float* red   = Vs + 2 * NN;           // [256]

    const int tid = threadIdx.x;
    const int i   = tid & 127;
    const int sub = tid >> 7;
    const int b   = blockIdx.x * 2 + sub;

    if (tid < NN) invCs[tid] = 1.f / C[tid];

    float4 yv = reinterpret_cast<const float4*>(y)[b * NN + i];
    float V = yv.x, m = yv.y, h = yv.z, n = yv.w;
    Vs[sub * NN + i] = V;
    __syncthreads();

    float colacc = 0.f;
    #pragma unroll 8
    for (int e = tid; e < NN * NN; e += 256) {
        float v = gC[e] * invCs[e & 127];
        w[e] = v;
        colacc += v;
    }
    __syncthreads();

    if (tid < NN)
        g_negGCC[blockIdx.x * NN + tid] = -w[blockIdx.x * NN + tid];

    if (blockIdx.x == 0) {
        red[tid] = colacc;
        __syncthreads();
        #pragma unroll
        for (int s = 128; s > 0; s >>= 1) {
            if (tid < s) red[tid] += red[tid + s];
            __syncthreads();
        }
        if (tid == 0) g_sumGC = red[0];
    }

    const float* wrow = w + i * NN;
    const float* vsub = Vs + sub * NN;
    float a0 = 0.f, a1 = 0.f, a2 = 0.f, a3 = 0.f;
    #pragma unroll 8
    for (int k = 0; k < NN; k += 4) {
        int j0 = (k + 0 + i) & 127;
        int j1 = (k + 1 + i) & 127;
        int j2 = (k + 2 + i) & 127;
        int j3 = (k + 3 + i) & 127;
        a0 = fmaf(wrow[j0], V - vsub[j0], a0);
        a1 = fmaf(wrow[j1], V - vsub[j1], a1);
        a2 = fmaf(wrow[j2], V - vsub[j2], a2);
        a3 = fmaf(wrow[j3], V - vsub[j3], a3);
    }
    float acc = (a0 + a1) + (a2 + a3);

    const float invC = invCs[i];
    float gna = g_Na[i], gk = g_K[i], gl = g_L[i];
    float m2 = m * m, m3 = m2 * m;
    float n2 = n * n, n3 = n2 * n, n4 = n3 * n;
    float dVNa = V - E_Na[i];
    float dVK  = V - E_K[i];

    float Vdot = invC * (-gna * m3 * h * dVNa - gk * n4 * dVK - gl * (V - E_L[i]) + Ic[b]) + acc;
    float mdot = (m_inf[i] - m) / tau_m[i];
    float hdot = (h_inf[i] - h) / tau_h[i];
    float ndot = (n_inf[i] - n) / tau_n[i];

    reinterpret_cast<float4*>(ydot)[b * NN + i] = make_float4(Vdot, mdot, hdot, ndot);

    float dvv = invC * (-gl - gna * h * m3 - gk * n4);
    float jm  = -invC * 3.f * gna * h * m2 * dVNa;
    float jh  = -invC * gna * m3 * dVNa;
    float jn  = -invC * 4.f * gk * n3 * dVK;
    g_state[b * NN + i] = make_float4(dvv, jm, jh, jn);
}

// ---------------------------------------------------------------------
// Kernel Z: zero-rows of J (comp in {1,2,3}; 384 rows; 201 MB).
// NO dependencies (reads tau inputs directly for the diagonal).
// PROVEN store structure: grid x = 192 zero-row-pairs, y = 128 batch
// pairs; 256 threads; each thread 2 float4 stores (b, b+128).
// Zero-row z -> i = z/3, c = z%3, r = 4i+1+c, comp = 1+c.
// ---------------------------------------------------------------------
__global__ void __launch_bounds__(256)
fill_zeros_kernel(float* __restrict__ J,
                  const float* __restrict__ tau_m,
                  const float* __restrict__ tau_h,
                  const float* __restrict__ tau_n) {
    const int j    = threadIdx.x & 127;
    const int half = threadIdx.x >> 7;
    const int z    = blockIdx.x * 2 + half;       // 0..383, warp-uniform
    const int i    = z / 3;
    const int c    = z - 3 * i;                   // 0..2
    const int r    = 4 * i + 1 + c;
    const int comp = 1 + c;
    const int b    = blockIdx.y;                  // batches b and b+128

    float4 o = make_float4(0.f, 0.f, 0.f, 0.f);
    if (j == i) {
        const float* tau = (comp == 1) ? tau_m : (comp == 2) ? tau_h : tau_n;
        reinterpret_cast<float*>(&o)[comp] = -1.f / tau[i];
    }

    unsigned idx0 = (unsigned)b * (EE * NN) + (unsigned)r * NN + j;
    unsigned idx1 = idx0 + 128u * (EE * NN);
    __stcs(reinterpret_cast<float4*>(J) + idx0, o);
    __stcs(reinterpret_cast<float4*>(J) + idx1, o);
}

// ---------------------------------------------------------------------
// Kernel V: V-rows of J (comp==0; 128 rows; 67 MB). Needs point output.
// PROVEN store structure: grid x = 64 neuron-pairs, y = 128 batch pairs;
// 256 threads; each thread 2 float4 stores (b, b+128).
// ---------------------------------------------------------------------
__global__ void __launch_bounds__(256)
fill_vrows_kernel(float* __restrict__ J) {
    const int j    = threadIdx.x & 127;
    const int half = threadIdx.x >> 7;
    const int i    = blockIdx.x * 2 + half;       // neuron 0..127, warp-uniform
    const int r    = 4 * i;
    const int b    = blockIdx.y;                  // batches b and b+128

    float4 o0 = make_float4(g_negGCC[i * NN + j], 0.f, 0.f, 0.f);
    float4 o1 = o0;

    if (j == i) {
        float s = g_sumGC;
        float4 s0 = g_state[b * NN + i];
        float4 s1 = g_state[(b + 128) * NN + i];
        o0.x += s + s0.x; o0.y = s0.y; o0.z = s0.z; o0.w = s0.w;
        o1.x += s + s1.x; o1.y = s1.y; o1.z = s1.z; o1.w = s1.w;
    }

    unsigned idx0 = (unsigned)b * (EE * NN) + (unsigned)r * NN + j;
    unsigned idx1 = idx0 + 128u * (EE * NN);
    __stcs(reinterpret_cast<float4*>(J) + idx0, o0);
    __stcs(reinterpret_cast<float4*>(J) + idx1, o1);
}

// ---------------------------------------------------------------------
extern "C" void kernel_launch(void* const* d_in, const int* in_sizes, int n_in,
                              void* d_out, int out_size) {
    const float* y     = (const float*)d_in[0];
    const float* Ic    = (const float*)d_in[1];
    const float* C     = (const float*)d_in[2];
    const float* g_Na  = (const float*)d_in[3];
    const float* E_Na  = (const float*)d_in[4];
    const float* g_K   = (const float*)d_in[5];
    const float* E_K   = (const float*)d_in[6];
    const float* g_L   = (const float*)d_in[7];
    const float* E_L   = (const float*)d_in[8];
    const float* m_inf = (const float*)d_in[9];
    const float* tau_m = (const float*)d_in[10];
    const float* h_inf = (const float*)d_in[11];
    const float* tau_h = (const float*)d_in[12];
    const float* n_inf = (const float*)d_in[13];
    const float* tau_n = (const float*)d_in[14];
    const float* g_C   = (const float*)d_in[15];

    float* out  = (float*)d_out;
    float* ydot = out;                       // B*512 floats
    float* J    = out + (size_t)BB * EE;     // B*512*512 floats

    const int smemBytes = (NN * NN + NN + 2 * NN + 256) * sizeof(float);
    cudaFuncSetAttribute(point_kernel,
                         cudaFuncAttributeMaxDynamicSharedMemorySize, smemBytes);

    // Fork both worker streams off the launch stream.
    cudaEventRecord(g_eFork, 0);
    cudaStreamWaitEvent(g_sA, g_eFork, 0);
    cudaStreamWaitEvent(g_sB, g_eFork, 0);

    // Branch B: point (~4 us) — hidden under branch A's 201 MB stream.
    point_kernel<<<BB / 2, 256, smemBytes, g_sB>>>(
        y, Ic, C, g_Na, E_Na, g_K, E_K, g_L, E_L,
        m_inf, tau_m, h_inf, tau_h, n_inf, tau_n, g_C, ydot);
    cudaEventRecord(g_eJoinB, g_sB);

    // Branch A: dependency-free zero rows (201 MB).
    fill_zeros_kernel<<<dim3(192, BB / 2), 256, 0, g_sA>>>(J, tau_m, tau_h, tau_n);

    // Join, then the V rows (67 MB).
    cudaStreamWaitEvent(g_sA, g_eJoinB, 0);
    fill_vrows_kernel<<<dim3(NN / 2, BB / 2), 256, 0, g_sA>>>(J);

    cudaEventRecord(g_eDone, g_sA);
    cudaStreamWaitEvent(0, g_eDone, 0);
}